// round 13
// baseline (speedup 1.0000x reference)
#include <cuda_runtime.h>
#include <cuda_fp16.h>
#include <cuda_bf16.h>
#include <cstdint>

#define NN 4096
#define FIN 128
#define FF 64
#define HH 8
#define MAXDEG 512
#define LOG2E 1.44269504088896f

// scratch (allocation-free rule: device globals)
__device__ float  g_feats[HH * NN * FF];     // fp32 [h][n][f] (for scores)
__device__ __half g_featsB[HH * NN * FF];    // fp16 [h][n][f] (MMA B source)
__device__ float  g_sself[HH * NN];          // pre-scaled by log2e
__device__ float  g_sneigh[HH * NN];         // pre-scaled by log2e
__device__ int    g_nbr[NN * MAXDEG];        // sorted neighbor lists (CSR)
__device__ int    g_tcnt[NN * 32];           // edges per (node, 128-m-tile)

__device__ __forceinline__ float ex2f(float x) {
    float r; asm("ex2.approx.ftz.f32 %0, %1;" : "=f"(r) : "f"(x)); return r;
}
__device__ __forceinline__ uint32_t smem_u32(const void* p) {
    uint32_t a;
    asm("{ .reg .u64 t; cvta.to.shared.u64 t, %1; cvt.u32.u64 %0, t; }" : "=r"(a) : "l"(p));
    return a;
}
__device__ __forceinline__ void cp16(uint32_t dst, const void* src) {
    asm volatile("cp.async.cg.shared.global [%0], [%1], 16;" :: "r"(dst), "l"(src));
}

// ---------------------------------------------------------------------------
// Kernel A: feats[h] = X @ W[h]. 64x64 tile, 256 thr, 4x4/thread, K-chunk 32.
// ---------------------------------------------------------------------------
__global__ __launch_bounds__(256) void gemm_feats_kernel(
    const float* __restrict__ X, const float* __restrict__ W)
{
    __shared__ float Xs[32 * 68];
    __shared__ float Ws[32 * 68];

    const int h  = blockIdx.y;
    const int r0 = blockIdx.x * 64;
    const int tid = threadIdx.x;
    const int tx = tid & 15;
    const int ty = tid >> 4;

    float acc[4][4];
#pragma unroll
    for (int i = 0; i < 4; i++)
#pragma unroll
        for (int j = 0; j < 4; j++) acc[i][j] = 0.0f;

    for (int kc = 0; kc < FIN; kc += 32) {
        for (int i = tid; i < 64 * 8; i += 256) {
            int r = i >> 3, kq = (i & 7) * 4;
            float4 v = *(const float4*)(X + (r0 + r) * FIN + kc + kq);
            Xs[(kq + 0) * 68 + r] = v.x;
            Xs[(kq + 1) * 68 + r] = v.y;
            Xs[(kq + 2) * 68 + r] = v.z;
            Xs[(kq + 3) * 68 + r] = v.w;
        }
        for (int i = tid; i < 32 * 16; i += 256) {
            int k = i >> 4, fq = (i & 15) * 4;
            float4 v = *(const float4*)(W + h * FIN * FF + (kc + k) * FF + fq);
            *(float4*)(Ws + k * 68 + fq) = v;
        }
        __syncthreads();
#pragma unroll
        for (int k = 0; k < 32; k++) {
            float4 a = *(const float4*)(Xs + k * 68 + ty * 4);
            float4 b = *(const float4*)(Ws + k * 68 + tx * 4);
            float av[4] = {a.x, a.y, a.z, a.w};
            float bv[4] = {b.x, b.y, b.z, b.w};
#pragma unroll
            for (int i = 0; i < 4; i++)
#pragma unroll
                for (int j = 0; j < 4; j++) acc[i][j] += av[i] * bv[j];
        }
        __syncthreads();
    }
#pragma unroll
    for (int i = 0; i < 4; i++) {
        int n = r0 + ty * 4 + i;
        *(float4*)(g_feats + (h * NN + n) * FF + tx * 4) =
            make_float4(acc[i][0], acc[i][1], acc[i][2], acc[i][3]);
        __half2 p0 = __floats2half2_rn(acc[i][0], acc[i][1]);
        __half2 p1 = __floats2half2_rn(acc[i][2], acc[i][3]);
        uint2 u = make_uint2(*(uint32_t*)&p0, *(uint32_t*)&p1);
        *(uint2*)(g_featsB + (h * NN + n) * FF + tx * 4) = u;
    }
}

// ---------------------------------------------------------------------------
// Kernel B: scores (pre-scaled by log2e). one warp per (h,n).
// ---------------------------------------------------------------------------
__global__ __launch_bounds__(256) void score_kernel(
    const float* __restrict__ a_self, const float* __restrict__ a_neigh)
{
    const int warp = threadIdx.x >> 5;
    const int lane = threadIdx.x & 31;
    const int p = blockIdx.x * 8 + warp;       // p = h*NN + n
    const int h = p >> 12;

    float v0 = g_feats[p * FF + lane];
    float v1 = g_feats[p * FF + lane + 32];
    float ss = v0 * a_self[h * FF + lane]  + v1 * a_self[h * FF + lane + 32];
    float sn = v0 * a_neigh[h * FF + lane] + v1 * a_neigh[h * FF + lane + 32];
#pragma unroll
    for (int o = 16; o; o >>= 1) {
        ss += __shfl_xor_sync(0xffffffffu, ss, o);
        sn += __shfl_xor_sync(0xffffffffu, sn, o);
    }
    if (lane == 0) { g_sself[p] = ss * LOG2E; g_sneigh[p] = sn * LOG2E; }
}

// ---------------------------------------------------------------------------
// Kernel C1: sorted neighbor compaction + per-128-tile edge counts.
// ---------------------------------------------------------------------------
__global__ __launch_bounds__(256) void compact_kernel(const int* __restrict__ A)
{
    const int warp = threadIdx.x >> 5;
    const int lane = threadIdx.x & 31;
    const int n = blockIdx.x * 8 + warp;
    const long long rb = (long long)n * NN;

    int base = 0, tcnt = 0;
    for (int i = 0; i < NN / 32; i++) {
        int a = A[rb + i * 32 + lane];
        unsigned mask = __ballot_sync(0xffffffffu, a != 0);
        int c = __popc(mask);
        if (a) {
            int pos = base + __popc(mask & ((1u << lane) - 1));
            if (pos < MAXDEG) g_nbr[n * MAXDEG + pos] = i * 32 + lane;
        }
        base += c;
        tcnt += c;
        if ((i & 3) == 3) {
            if (lane == 0) g_tcnt[n * 32 + (i >> 2)] = tcnt;
            tcnt = 0;
        }
    }
}

// ---------------------------------------------------------------------------
// Kernel C2: warp-MMA attention aggregation (fp16 HMMA, fp32 accumulate).
// grid (NN/128, HH) = (32, 8), 256 threads, 2 CTAs/SM (one full wave).
// n-tile 128, warp tile 32x32 (4 row-blocks x 2 col-halves).
// Per 128-m tile: unscatter prev P entries (register-remembered), probe CSR
// (2 thr/row, prestaged counts), scatter exp2 weights into persistent P,
// cp.async double-buffered F, double-buffered sneigh, then m16n8k16 MMAs.
// ---------------------------------------------------------------------------
#define PS 136                       // P row stride (halfs); 272B
#define FS 72                        // F row stride (halfs); 144B
#define SM_PTR 0                     // int[128]
#define SM_SS  512                   // float[128]
#define SM_SUM 1024                  // float[128]
#define SM_SNB 1536                  // float[2][128]
#define SM_CNT 2560                  // short[128*32] = 8KB
#define SM_P   10752                 // 128*272 = 34816
#define SM_F0  45568                 // 128*144 = 18432
#define SM_F1  64000
#define SM_TOTAL 82432

__global__ __launch_bounds__(256) void attn_mma_kernel(
    const float* __restrict__ bias, float* __restrict__ out)
{
    extern __shared__ char smem[];
    int*    sPtr = (int*)(smem + SM_PTR);
    float*  sSS  = (float*)(smem + SM_SS);
    float*  sSum = (float*)(smem + SM_SUM);
    float*  sSnb = (float*)(smem + SM_SNB);     // [2][128]
    short*  sCnt = (short*)(smem + SM_CNT);     // [128][32]
    __half* sP   = (__half*)(smem + SM_P);
    const uint32_t sb = smem_u32(smem);

    const int tid  = threadIdx.x;
    const int wid  = tid >> 5;
    const int lane = tid & 31;
    const int h  = blockIdx.y;
    const int n0 = blockIdx.x * 128;

    const int r0 = (wid & 3) * 32;       // MMA row block (32 rows)
    const int cb = (wid >> 2) * 32;      // MMA col half

    const int prow = tid >> 1;           // probe: row 0..127
    const int psl  = tid & 1;            // probe: slot 0..1
    const int pn   = n0 + prow;

    if (tid < 128) {
        sPtr[tid] = 0;
        sSum[tid] = 0.0f;
        sSS[tid]  = g_sself[h * NN + n0 + tid];
        sSnb[tid] = g_sneigh[h * NN + tid];          // tile 0, buf 0
    }
    // prestage per-tile counts (128 rows x 32 tiles)
    for (int i = tid; i < 128 * 32; i += 256)
        sCnt[i] = (short)g_tcnt[(n0 + (i >> 5)) * 32 + (i & 31)];
    // initial full P zero (persistent across tiles; unscatter keeps it clean)
    for (int i = tid; i < 128 * 17; i += 256)
        *(int4*)(smem + SM_P + (i / 17) * (PS * 2) + (i % 17) * 16) =
            make_int4(0, 0, 0, 0);

    float d[2][4][4];
#pragma unroll
    for (int mf = 0; mf < 2; mf++)
#pragma unroll
        for (int j = 0; j < 4; j++)
#pragma unroll
            for (int k = 0; k < 4; k++) d[mf][j][k] = 0.0f;

    const float* __restrict__ snb = g_sneigh + h * NN;

    // ldmatrix base addresses
    const uint32_t aA0 = sb + SM_P +
        (uint32_t)(((r0 + (lane & 15)) * PS + ((lane >> 4) << 3)) * 2);
    const uint32_t aA1 = aA0 + 16 * PS * 2;
    const uint32_t bCol = (uint32_t)((((lane & 7) + ((lane >> 3) & 1) * 8) * FS +
                                     ((lane >> 4) << 3) + cb) * 2);

    // prologue: stage F tile 0 into F0
#pragma unroll
    for (int it = 0; it < 4; it++) {
        int i = tid + it * 256;
        int m = i >> 3, q = i & 7;
        cp16(sb + SM_F0 + (uint32_t)(m * (FS * 2) + q * 16),
             g_featsB + (h * NN + m) * FF + q * 8);
    }
    asm volatile("cp.async.commit_group;" ::: "memory");

    // unscatter state (previous tile's scattered columns)
    int pcols[6];
    int povf = 0;                 // overflow count (cnt-12 if >0)
    const int* pnbp = g_nbr;      // prev CSR base (for overflow rezero)
    int pfast = 0;                // fast-path scatter count for this thread

    for (int mt = 0; mt < 32; mt++) {
        const int mb = mt * 128;
        const int buf = mt & 1;

        __syncthreads();   // previous MMA done: P writable

        // --- unscatter previous tile's entries ---
        {
#pragma unroll
            for (int t = 0; t < 6; t++)
                if (t < pfast) sP[prow * PS + pcols[t]] = __float2half(0.0f);
            for (int j = 12 + psl; j < 12 + povf * 2 + psl; ) { // dummy guard shape
                break;
            }
            if (povf > 0) {
                for (int j = 12 + psl; j < 12 + povf; j += 2)
                    sP[prow * PS + (pnbp[j] & 127)] = __float2half(0.0f);
            }
        }
        __syncthreads();   // P clean before new scatter

        // --- probe + scatter (2 threads per row) ---
        {
            int cnt  = (int)sCnt[prow * 32 + mt];
            int ptrv = sPtr[prow];
            const int* nbp = g_nbr + pn * MAXDEG + ptrv;
            float ssv = sSS[prow];
            const float* snbT = sSnb + buf * 128;
            float esum = 0.0f;

            int ms[6];
#pragma unroll
            for (int t = 0; t < 6; t++) {
                int j = psl + t * 2;
                ms[t] = (j < cnt) ? nbp[j] : mb;
            }
            pfast = 0;
#pragma unroll
            for (int t = 0; t < 6; t++) {
                int j = psl + t * 2;
                if (j < cnt) {
                    int col = ms[t] - mb;
                    float sc = ssv + snbT[col];
                    sc = sc > 0.0f ? sc : 0.2f * sc;
                    float e = ex2f(sc);
                    esum += e;
                    sP[prow * PS + col] = __float2half(e);
                    pcols[pfast++] = col;
                }
            }
            // overflow path (rare)
            for (int j = 12 + psl; j < cnt; j += 2) {
                int col = nbp[j] - mb;
                float sc = ssv + snbT[col];
                sc = sc > 0.0f ? sc : 0.2f * sc;
                float e = ex2f(sc);
                esum += e;
                sP[prow * PS + col] = __float2half(e);
            }
            povf = cnt > 12 ? (cnt - 12) : 0;
            pnbp = nbp;  // overflow rezero re-reads CSR; cols = (nbr - mb) = low 7 bits
            esum += __shfl_xor_sync(0xffffffffu, esum, 1);
            if (psl == 0) {
                sSum[prow] += esum;
                sPtr[prow] = ptrv + cnt;
            }
        }

        // --- stage next F tile (overlaps with MMA via cp.async) ---
        if (mt < 31) {
            uint32_t fb = sb + (buf ? SM_F0 : SM_F1);
            const int mbn = (mt + 1) * 128;
#pragma unroll
            for (int it = 0; it < 4; it++) {
                int i = tid + it * 256;
                int m = i >> 3, q = i & 7;
                cp16(fb + (uint32_t)(m * (FS * 2) + q * 16),
                     g_featsB + (h * NN + mbn + m) * FF + q * 8);
            }
            asm volatile("cp.async.commit_group;" ::: "memory");
            asm volatile("cp.async.wait_group 1;" ::: "memory");
        } else {
            asm volatile("cp.async.wait_group 0;" ::: "memory");
        }
        __syncthreads();   // P scattered + F[buf] arrived

        // stage next sneigh tile concurrently with MMA
        if (mt < 31 && tid < 128)
            sSnb[(1 - buf) * 128 + tid] = snb[(mt + 1) * 128 + tid];

        // --- MMA: D[32,32] += P[32,128] @ F[128,32] ---
        const uint32_t bAddr0 = sb + (buf ? SM_F1 : SM_F0) + bCol;
#pragma unroll
        for (int ks = 0; ks < 8; ks++) {
            uint32_t a0, a1, a2, a3, a4, a5, a6, a7;
            asm volatile("ldmatrix.sync.aligned.m8n8.x4.shared.b16 {%0,%1,%2,%3}, [%4];"
                : "=r"(a0), "=r"(a1), "=r"(a2), "=r"(a3)
                : "r"(aA0 + ks * 32));
            asm volatile("ldmatrix.sync.aligned.m8n8.x4.shared.b16 {%0,%1,%2,%3}, [%4];"
                : "=r"(a4), "=r"(a5), "=r"(a6), "=r"(a7)
                : "r"(aA1 + ks * 32));
#pragma unroll
            for (int nf = 0; nf < 2; nf++) {
                uint32_t b0, b1, b2, b3;
                asm volatile("ldmatrix.sync.aligned.m8n8.x4.trans.shared.b16 {%0,%1,%2,%3}, [%4];"
                    : "=r"(b0), "=r"(b1), "=r"(b2), "=r"(b3)
                    : "r"(bAddr0 + (uint32_t)(ks * 16 * (FS * 2) + nf * 32)));
                asm volatile(
                    "mma.sync.aligned.m16n8k16.row.col.f32.f16.f16.f32 "
                    "{%0,%1,%2,%3}, {%4,%5,%6,%7}, {%8,%9}, {%0,%1,%2,%3};"
                    : "+f"(d[0][nf*2][0]), "+f"(d[0][nf*2][1]), "+f"(d[0][nf*2][2]), "+f"(d[0][nf*2][3])
                    : "r"(a0), "r"(a1), "r"(a2), "r"(a3), "r"(b0), "r"(b1));
                asm volatile(
                    "mma.sync.aligned.m16n8k16.row.col.f32.f16.f16.f32 "
                    "{%0,%1,%2,%3}, {%4,%5,%6,%7}, {%8,%9}, {%0,%1,%2,%3};"
                    : "+f"(d[0][nf*2+1][0]), "+f"(d[0][nf*2+1][1]), "+f"(d[0][nf*2+1][2]), "+f"(d[0][nf*2+1][3])
                    : "r"(a0), "r"(a1), "r"(a2), "r"(a3), "r"(b2), "r"(b3));
                asm volatile(
                    "mma.sync.aligned.m16n8k16.row.col.f32.f16.f16.f32 "
                    "{%0,%1,%2,%3}, {%4,%5,%6,%7}, {%8,%9}, {%0,%1,%2,%3};"
                    : "+f"(d[1][nf*2][0]), "+f"(d[1][nf*2][1]), "+f"(d[1][nf*2][2]), "+f"(d[1][nf*2][3])
                    : "r"(a4), "r"(a5), "r"(a6), "r"(a7), "r"(b0), "r"(b1));
                asm volatile(
                    "mma.sync.aligned.m16n8k16.row.col.f32.f16.f16.f32 "
                    "{%0,%1,%2,%3}, {%4,%5,%6,%7}, {%8,%9}, {%0,%1,%2,%3};"
                    : "+f"(d[1][nf*2+1][0]), "+f"(d[1][nf*2+1][1]), "+f"(d[1][nf*2+1][2]), "+f"(d[1][nf*2+1][3])
                    : "r"(a4), "r"(a5), "r"(a6), "r"(a7), "r"(b2), "r"(b3));
            }
        }
    }
    __syncthreads();

    // --- epilogue: normalize, bias, ELU, store ---
    {
        const int g  = lane >> 2;
        const int cq = (lane & 3) * 2;
#pragma unroll
        for (int mf = 0; mf < 2; mf++) {
            const int rowA = r0 + mf * 16 + g;
            const int rowB = rowA + 8;
            const float invA = 1.0f / sSum[rowA];
            const float invB = 1.0f / sSum[rowB];
            const int nA = n0 + rowA;
            const int nB = n0 + rowB;
#pragma unroll
            for (int j = 0; j < 4; j++) {
                int c = cb + j * 8 + cq;
                float bs0 = __ldg(bias + h * FF + c);
                float bs1 = __ldg(bias + h * FF + c + 1);
                float vA0 = d[mf][j][0] * invA + bs0;
                float vA1 = d[mf][j][1] * invA + bs1;
                float vB0 = d[mf][j][2] * invB + bs0;
                float vB1 = d[mf][j][3] * invB + bs1;
                vA0 = vA0 > 0.0f ? vA0 : expm1f(vA0);
                vA1 = vA1 > 0.0f ? vA1 : expm1f(vA1);
                vB0 = vB0 > 0.0f ? vB0 : expm1f(vB0);
                vB1 = vB1 > 0.0f ? vB1 : expm1f(vB1);
                *(float2*)(out + nA * (HH * FF) + h * FF + c) = make_float2(vA0, vA1);
                *(float2*)(out + nB * (HH * FF) + h * FF + c) = make_float2(vB0, vB1);
            }
        }
    }
}

// ---------------------------------------------------------------------------
extern "C" void kernel_launch(void* const* d_in, const int* in_sizes, int n_in,
                              void* d_out, int out_size)
{
    const float* X       = (const float*)d_in[0];   // [4096,128]
    const int*   A       = (const int*)  d_in[1];   // [4096,4096]
    const float* W       = (const float*)d_in[2];   // [8,128,64]
    const float* b       = (const float*)d_in[3];   // [8,64]
    const float* a_self  = (const float*)d_in[4];   // [8,64]
    const float* a_neigh = (const float*)d_in[5];   // [8,64]
    float* out = (float*)d_out;                     // [4096, 512]

    static bool attr_set = false;
    if (!attr_set) {
        cudaFuncSetAttribute(attn_mma_kernel,
                             cudaFuncAttributeMaxDynamicSharedMemorySize, SM_TOTAL);
        attr_set = true;
    }

    gemm_feats_kernel<<<dim3(NN / 64, HH), 256>>>(X, W);
    score_kernel<<<NN, 256>>>(a_self, a_neigh);
    compact_kernel<<<NN / 8, 256>>>(A);
    attn_mma_kernel<<<dim3(NN / 128, HH), 256, SM_TOTAL>>>(b, out);
}